// round 4
// baseline (speedup 1.0000x reference)
#include <cuda_runtime.h>
#include <cstdint>

// AttentionMV: B=T=1024, E=128
//   u   = tanh(m[b] @ W[b] + bias)       (T,E)
//   pre = v^T @ u                        (E,E)
//   alpha = softmax(pre, axis=-1)
//   out[b] = colsum(m[b]) @ alpha
// Fused, one CTA per batch. FFMA2 (fma.rn.f32x2) inner loops, conflict-free
// lane mapping (thread owns cols lane*4..+4), 2 CTAs/SM.

constexpr int Bn = 1024;
constexpr int Tn = 1024;
constexpr int En = 128;
constexpr int TT = 32;          // time tile
constexpr int NTHREADS = 256;   // 8 warps

constexpr int SMEM_FLOATS = En * En + 2 * TT * En + 2 * En;
constexpr size_t SMEM_BYTES = SMEM_FLOATS * sizeof(float);

typedef unsigned long long u64;

__device__ __forceinline__ u64 ffma2(u64 a, u64 b, u64 c) {
    u64 d;
    asm("fma.rn.f32x2 %0, %1, %2, %3;" : "=l"(d) : "l"(a), "l"(b), "l"(c));
    return d;
}
__device__ __forceinline__ u64 pack2(float x) {
    u64 d;
    unsigned xu = __float_as_uint(x);
    asm("mov.b64 %0, {%1, %1};" : "=l"(d) : "r"(xu));
    return d;
}
__device__ __forceinline__ void unpack2(u64 v, float& lo, float& hi) {
    unsigned a, b;
    asm("mov.b64 {%0, %1}, %2;" : "=r"(a), "=r"(b) : "l"(v));
    lo = __uint_as_float(a);
    hi = __uint_as_float(b);
}

__device__ __forceinline__ float fast_tanh(float x) {
    float e = __expf(2.0f * x);
    return 1.0f - __fdividef(2.0f, e + 1.0f);
}

__global__ __launch_bounds__(NTHREADS, 2)
void attn_mv_kernel(const float* __restrict__ gm, const float* __restrict__ gv,
                    const float* __restrict__ gW, const float* __restrict__ gb,
                    float* __restrict__ gout)
{
    extern __shared__ float smem[];
    float* Ws   = smem;              // [128][128]
    float* ms   = Ws + En * En;      // [TT][128]
    float* us   = ms + TT * En;      // [TT][128]
    float* ssum = us + TT * En;      // [128] column sums of m[b]
    float* red  = ssum + En;         // [128] output reduction

    const int bb   = blockIdx.x;
    const int tid  = threadIdx.x;
    const int lane = tid & 31;       // owns cols lane*4..lane*4+3
    const int w    = tid >> 5;       // warp 0..7

    const float* Wb = gW + (size_t)bb * En * En;
    const float* mb = gm + (size_t)bb * Tn * En;

    // Load W[b] into SMEM
    #pragma unroll
    for (int i = 0; i < (En * En) / (NTHREADS * 4); i++) {
        int off = (i * NTHREADS + tid) * 4;
        *reinterpret_cast<float4*>(Ws + off) =
            *reinterpret_cast<const float4*>(Wb + off);
    }
    if (tid < En) { ssum[tid] = 0.0f; red[tid] = 0.0f; }

    // pre accumulators: warp w owns e-rows w*16..+15; thread owns f=lane*4..+3
    u64 pre2[16][2];
    #pragma unroll
    for (int i = 0; i < 16; i++) { pre2[i][0] = 0ull; pre2[i][1] = 0ull; }

    for (int t0 = 0; t0 < Tn; t0 += TT) {
        __syncthreads();  // A: prev iter done with ms/us

        // Load m tile (TT*128 floats; 4 float4 per thread, coalesced)
        #pragma unroll
        for (int i = 0; i < (TT * En) / (NTHREADS * 4); i++) {
            int off = (i * NTHREADS + tid) * 4;
            *reinterpret_cast<float4*>(ms + off) =
                *reinterpret_cast<const float4*>(mb + (size_t)t0 * En + off);
        }
        __syncthreads();  // B

        // Column sums of m tile (lanes consecutive -> conflict-free)
        if (tid < En) {
            float acc = 0.0f;
            #pragma unroll
            for (int t = 0; t < TT; t++) acc += ms[t * En + tid];
            ssum[tid] += acc;
        }

        // ---- GEMM1: warp w computes u rows t' = w*4..+3, cols lane*4..+3
        u64 ua[4][2];
        #pragma unroll
        for (int i = 0; i < 4; i++) {
            int tg = t0 + w * 4 + i;   // bias indexed by global time (T==B)
            const float* bp = gb + (size_t)tg * En + lane * 4;
            ua[i][0] = *reinterpret_cast<const u64*>(bp);
            ua[i][1] = *reinterpret_cast<const u64*>(bp + 2);
        }
        #pragma unroll 4
        for (int k = 0; k < En; k += 4) {
            u64 ap[4][4];
            #pragma unroll
            for (int i = 0; i < 4; i++) {
                float4 t4 = *reinterpret_cast<const float4*>(ms + (w * 4 + i) * En + k);
                ap[i][0] = pack2(t4.x); ap[i][1] = pack2(t4.y);
                ap[i][2] = pack2(t4.z); ap[i][3] = pack2(t4.w);
            }
            #pragma unroll
            for (int kk = 0; kk < 4; kk++) {
                ulonglong2 wv = *reinterpret_cast<const ulonglong2*>(
                    Ws + (k + kk) * En + lane * 4);
                #pragma unroll
                for (int i = 0; i < 4; i++) {
                    ua[i][0] = ffma2(ap[i][kk], wv.x, ua[i][0]);
                    ua[i][1] = ffma2(ap[i][kk], wv.y, ua[i][1]);
                }
            }
        }
        // tanh + store u tile
        #pragma unroll
        for (int i = 0; i < 4; i++) {
            float x0, x1, x2, x3;
            unpack2(ua[i][0], x0, x1);
            unpack2(ua[i][1], x2, x3);
            float4 o;
            o.x = fast_tanh(x0); o.y = fast_tanh(x1);
            o.z = fast_tanh(x2); o.w = fast_tanh(x3);
            *reinterpret_cast<float4*>(us + (w * 4 + i) * En + lane * 4) = o;
        }
        __syncthreads();  // C: u tile ready

        // ---- GEMM2: pre[e][f] += v[t][e] * u[t][f], e = w*16..+15
        const float* vbase = gv + (size_t)t0 * En + w * 16;
        #pragma unroll 2
        for (int t = 0; t < TT; t++) {
            ulonglong2 u2 = *reinterpret_cast<const ulonglong2*>(
                us + t * En + lane * 4);
            float4 v0 = __ldg(reinterpret_cast<const float4*>(vbase + t * En + 0));
            float4 v1 = __ldg(reinterpret_cast<const float4*>(vbase + t * En + 4));
            float4 v2 = __ldg(reinterpret_cast<const float4*>(vbase + t * En + 8));
            float4 v3 = __ldg(reinterpret_cast<const float4*>(vbase + t * En + 12));
            float vv[16] = {v0.x, v0.y, v0.z, v0.w, v1.x, v1.y, v1.z, v1.w,
                            v2.x, v2.y, v2.z, v2.w, v3.x, v3.y, v3.z, v3.w};
            #pragma unroll
            for (int i = 0; i < 16; i++) {
                u64 vp = pack2(vv[i]);
                pre2[i][0] = ffma2(vp, u2.x, pre2[i][0]);
                pre2[i][1] = ffma2(vp, u2.y, pre2[i][1]);
            }
        }
    }
    __syncthreads();

    // ---- Softmax over f per row e, weighted by ssum[e], reduced over e.
    // Row e = w*16+i spans the full warp (32 lanes x 4 cols).
    float acc[4] = {0.0f, 0.0f, 0.0f, 0.0f};

    #pragma unroll
    for (int i = 0; i < 16; i++) {
        float p[4];
        unpack2(pre2[i][0], p[0], p[1]);
        unpack2(pre2[i][1], p[2], p[3]);
        float mx = fmaxf(fmaxf(p[0], p[1]), fmaxf(p[2], p[3]));
        #pragma unroll
        for (int off = 16; off >= 1; off >>= 1)
            mx = fmaxf(mx, __shfl_xor_sync(0xffffffffu, mx, off));
        float ex[4];
        float sum = 0.0f;
        #pragma unroll
        for (int j = 0; j < 4; j++) { ex[j] = __expf(p[j] - mx); sum += ex[j]; }
        #pragma unroll
        for (int off = 16; off >= 1; off >>= 1)
            sum += __shfl_xor_sync(0xffffffffu, sum, off);
        float coef = ssum[w * 16 + i] * __fdividef(1.0f, sum);
        #pragma unroll
        for (int j = 0; j < 4; j++) acc[j] = fmaf(coef, ex[j], acc[j]);
    }
    #pragma unroll
    for (int j = 0; j < 4; j++) atomicAdd(&red[lane * 4 + j], acc[j]);
    __syncthreads();

    if (tid < En) gout[(size_t)bb * En + tid] = red[tid];
}

extern "C" void kernel_launch(void* const* d_in, const int* in_sizes, int n_in,
                              void* d_out, int out_size) {
    const float* m = (const float*)d_in[0];
    const float* v = (const float*)d_in[1];
    const float* W = (const float*)d_in[2];
    const float* b = (const float*)d_in[3];
    float* out = (float*)d_out;

    cudaFuncSetAttribute(attn_mv_kernel,
                         cudaFuncAttributeMaxDynamicSharedMemorySize,
                         (int)SMEM_BYTES);
    attn_mv_kernel<<<Bn, NTHREADS, SMEM_BYTES>>>(m, v, W, b, out);
}

// round 6
// speedup vs baseline: 2.3086x; 2.3086x over previous
#include <cuda_runtime.h>
#include <cuda_bf16.h>
#include <cstdint>

typedef unsigned int u32; typedef unsigned short u16;

// AttentionMV B=T=1024, E=128, via mma.sync bf16 (3-pass split) fallback HMMA.
//  GEMM1 (per 64-t tile): D1[f][t] = sum_e WT[f][e]*m[t][e]
//  u = tanh(D1 + b[t][f]) -> bf16 hi/lo in REGISTERS (D1 accum fragment layout
//  == GEMM2 B fragment layout, so u never touches smem)
//  GEMM2: pre[e][f] += sum_t vT[e][t]*u[t][f]   (accumulated in regs, all tiles)
//  softmax over f per e-row; out[f] = sum_e (colsum_e/sumexp_e)*exp(pre[e][f]-mx_e)

constexpr int NT = 256;
// smem byte offsets. WT stride 136 elem, m stride 136, vT stride 72.
constexpr u32 WTH=0, WTL=34816, MH=69632, ML=87040, VTH=104448, VTL=122880;
constexpr u32 SP_OFF=141312;          // 8*128 f32 colsum partials
constexpr u32 CF_OFF=SP_OFF+4096;     // 128 f32 coef
constexpr u32 SMEM_BYTES=CF_OFF+512+64;
constexpr u32 P_OFF=0;                // 128x132 f32 (aliases WT, post-loop)
constexpr u32 EX_OFF=69632;           // 128x132 f32 (aliases m/vT, post-loop)

__device__ u16 g_vtH[128*1024];
__device__ u16 g_vtL[128*1024];

__device__ __forceinline__ float fast_tanh(float x){
    float e = __expf(2.0f*x);
    return 1.0f - __fdividef(2.0f, e+1.0f);
}
__device__ __forceinline__ void bsplit(float x, u16& h, u16& l){
    __nv_bfloat16 hb = __float2bfloat16(x);
    h = __bfloat16_as_ushort(hb);
    l = __bfloat16_as_ushort(__float2bfloat16(x - __bfloat162float(hb)));
}
__device__ __forceinline__ void mma16816(float* d, u32 a0,u32 a1,u32 a2,u32 a3,
                                         u32 b0,u32 b1){
    asm volatile("mma.sync.aligned.m16n8k16.row.col.f32.bf16.bf16.f32 "
        "{%0,%1,%2,%3}, {%4,%5,%6,%7}, {%8,%9}, {%0,%1,%2,%3};"
        : "+f"(d[0]),"+f"(d[1]),"+f"(d[2]),"+f"(d[3])
        : "r"(a0),"r"(a1),"r"(a2),"r"(a3),"r"(b0),"r"(b1));
}

__global__ void vt_prep(const float* __restrict__ gv){
    int t = blockIdx.x, e = threadIdx.x;
    u16 h,l; bsplit(gv[t*128+e], h, l);
    g_vtH[e*1024+t]=h; g_vtL[e*1024+t]=l;
}

__global__ __launch_bounds__(NT,1)
void attn_mma(const float* __restrict__ gm, const float* __restrict__ gW,
              const float* __restrict__ gb, float* __restrict__ gout)
{
    extern __shared__ char sm[];
    const int tid=threadIdx.x, lane=tid&31, w=tid>>5, bb=blockIdx.x;
    const int q=lane>>2, r2=(lane&3)*2;
    const float* Wb = gW + (size_t)bb*16384;
    const float4* mb4 = (const float4*)(gm + (size_t)bb*131072);

    // W -> WT[f][e] hi/lo bf16 (transposed, stride 136)
    for (int idx=tid; idx<16384; idx+=NT){
        int e=idx>>7, f=idx&127;
        u16 h,l; bsplit(__ldg(Wb+idx), h, l);
        *(u16*)(sm + WTH + (u32)(f*136+e)*2) = h;
        *(u16*)(sm + WTL + (u32)(f*136+e)*2) = l;
    }

    float4 mreg[8];
    #pragma unroll
    for (int i=0;i<8;i++) mreg[i] = __ldg(mb4 + i*NT + tid);

    float pre[8][2][4];
    #pragma unroll
    for (int i=0;i<8;i++)
        #pragma unroll
        for (int fb=0;fb<2;fb++)
            #pragma unroll
            for (int j=0;j<4;j++) pre[i][fb][j]=0.f;
    float s4[4]={0,0,0,0};

    for (int tile=0; tile<16; tile++){
        // m regs -> smem hi/lo (row = i*8+w, cols lane*4..+3) + colsum
        #pragma unroll
        for (int i=0;i<8;i++){
            float4 x = mreg[i];
            s4[0]+=x.x; s4[1]+=x.y; s4[2]+=x.z; s4[3]+=x.w;
            u16 h0,l0,h1,l1,h2,l2,h3,l3;
            bsplit(x.x,h0,l0); bsplit(x.y,h1,l1);
            bsplit(x.z,h2,l2); bsplit(x.w,h3,l3);
            u32 off = (u32)((i*8+w)*136 + lane*4)*2;
            *(uint2*)(sm + MH + off) = make_uint2((u32)h0|((u32)h1<<16), (u32)h2|((u32)h3<<16));
            *(uint2*)(sm + ML + off) = make_uint2((u32)l0|((u32)l1<<16), (u32)l2|((u32)l3<<16));
        }
        // vT tile copy (gmem pre-split images, 4 bf16 per uint2)
        {
            const u16* srcH = g_vtH + tile*64;
            const u16* srcL = g_vtL + tile*64;
            #pragma unroll
            for (int i=0;i<8;i++){
                int j = i*NT + tid;           // 0..2047
                int e = j>>4, tq = (j&15)*4;
                *(uint2*)(sm + VTH + (u32)(e*72+tq)*2) = *(const uint2*)(srcH + e*1024 + tq);
                *(uint2*)(sm + VTL + (u32)(e*72+tq)*2) = *(const uint2*)(srcL + e*1024 + tq);
            }
        }
        __syncthreads();
        if (tile<15){
            #pragma unroll
            for (int i=0;i<8;i++) mreg[i] = __ldg(mb4 + (tile+1)*2048 + i*NT + tid);
        }

        // ---- GEMM1: warp w -> f rows w*16..+15, t cols 0..63 (8 n-blocks)
        float d1[8][4];
        #pragma unroll
        for (int nb=0;nb<8;nb++){ d1[nb][0]=0;d1[nb][1]=0;d1[nb][2]=0;d1[nb][3]=0; }
        #pragma unroll
        for (int ks=0;ks<8;ks++){
            u32 ar = (u32)((w*16+q)*136 + ks*16 + r2);
            u32 ah0=*(u32*)(sm+WTH+ar*2),        ah1=*(u32*)(sm+WTH+(ar+8*136)*2);
            u32 ah2=*(u32*)(sm+WTH+(ar+8)*2),    ah3=*(u32*)(sm+WTH+(ar+8*136+8)*2);
            u32 al0=*(u32*)(sm+WTL+ar*2),        al1=*(u32*)(sm+WTL+(ar+8*136)*2);
            u32 al2=*(u32*)(sm+WTL+(ar+8)*2),    al3=*(u32*)(sm+WTL+(ar+8*136+8)*2);
            #pragma unroll
            for (int nb=0;nb<8;nb++){
                u32 boff = (u32)((nb*8+q)*136 + ks*16 + r2)*2;
                u32 bh0=*(u32*)(sm+MH+boff), bh1=*(u32*)(sm+MH+boff+16);
                u32 bl0=*(u32*)(sm+ML+boff), bl1=*(u32*)(sm+ML+boff+16);
                mma16816(d1[nb], ah0,ah1,ah2,ah3, bh0,bh1);
                mma16816(d1[nb], ah0,ah1,ah2,ah3, bl0,bl1);
                mma16816(d1[nb], al0,al1,al2,al3, bh0,bh1);
            }
        }

        // ---- bias + tanh + bf16 split (registers only)
        // c0:(f0,t0) c1:(f0,t0+1) c2:(f0+8,t0) c3:(f0+8,t0+1)
        u32 uh[8][2], ul[8][2];
        #pragma unroll
        for (int nb=0;nb<8;nb++){
            int t0 = tile*64 + nb*8 + r2;
            int f0 = w*16 + q;
            const float* bp = gb + (size_t)t0*128;
            float u0=fast_tanh(d1[nb][0]+__ldg(bp+f0));
            float u1=fast_tanh(d1[nb][1]+__ldg(bp+128+f0));
            float u2=fast_tanh(d1[nb][2]+__ldg(bp+f0+8));
            float u3=fast_tanh(d1[nb][3]+__ldg(bp+128+f0+8));
            u16 h0,l0,h1,l1,h2,l2,h3,l3;
            bsplit(u0,h0,l0); bsplit(u1,h1,l1); bsplit(u2,h2,l2); bsplit(u3,h3,l3);
            uh[nb][0]=(u32)h0|((u32)h1<<16); ul[nb][0]=(u32)l0|((u32)l1<<16);
            uh[nb][1]=(u32)h2|((u32)h3<<16); ul[nb][1]=(u32)l2|((u32)l3<<16);
        }

        // ---- GEMM2: pre[e-block i][f-block fb] += vT x u
        #pragma unroll
        for (int i=0;i<8;i++){
            #pragma unroll
            for (int s=0;s<4;s++){
                u32 ar = (u32)((i*16+q)*72 + s*16 + r2);
                u32 ah0=*(u32*)(sm+VTH+ar*2),       ah1=*(u32*)(sm+VTH+(ar+8*72)*2);
                u32 ah2=*(u32*)(sm+VTH+(ar+8)*2),   ah3=*(u32*)(sm+VTH+(ar+8*72+8)*2);
                u32 al0=*(u32*)(sm+VTL+ar*2),       al1=*(u32*)(sm+VTL+(ar+8*72)*2);
                u32 al2=*(u32*)(sm+VTL+(ar+8)*2),   al3=*(u32*)(sm+VTL+(ar+8*72+8)*2);
                #pragma unroll
                for (int fb=0;fb<2;fb++){
                    mma16816(pre[i][fb], ah0,ah1,ah2,ah3, uh[2*s][fb], uh[2*s+1][fb]);
                    mma16816(pre[i][fb], ah0,ah1,ah2,ah3, ul[2*s][fb], ul[2*s+1][fb]);
                    mma16816(pre[i][fb], al0,al1,al2,al3, uh[2*s][fb], uh[2*s+1][fb]);
                }
            }
        }
        __syncthreads();   // protect mH/vT for next tile
    }

    // ---- epilogue: pre -> P smem (aliases WT, safe post-loop)
    float* P = (float*)(sm + P_OFF);
    #pragma unroll
    for (int i=0;i<8;i++)
        #pragma unroll
        for (int fb=0;fb<2;fb++){
            int e0 = i*16+q, f0 = w*16+fb*8+r2;
            P[e0*132+f0]     = pre[i][fb][0];
            P[e0*132+f0+1]   = pre[i][fb][1];
            P[(e0+8)*132+f0]   = pre[i][fb][2];
            P[(e0+8)*132+f0+1] = pre[i][fb][3];
        }
    float* SP=(float*)(sm+SP_OFF);
    *(float4*)(SP + w*128 + lane*4) = make_float4(s4[0],s4[1],s4[2],s4[3]);
    __syncthreads();

    float* EX=(float*)(sm+EX_OFF);
    float* CF=(float*)(sm+CF_OFF);
    if (tid<128){
        int e=tid;
        float ss=0;
        #pragma unroll
        for (int ww=0;ww<8;ww++) ss+=SP[ww*128+e];
        float mx=-1e30f;
        #pragma unroll 8
        for (int f=0;f<128;f++) mx=fmaxf(mx,P[e*132+f]);
        float sum=0;
        #pragma unroll 4
        for (int f=0;f<128;f++){
            float ex=__expf(P[e*132+f]-mx);
            sum+=ex; EX[f*132+e]=ex;
        }
        CF[e]=ss*__fdividef(1.f,sum);
    }
    __syncthreads();
    if (tid<128){
        int f=tid; float acc=0;
        #pragma unroll 8
        for (int e=0;e<128;e++) acc=fmaf(CF[e],EX[f*132+e],acc);
        gout[(size_t)bb*128+f]=acc;
    }
}

extern "C" void kernel_launch(void* const* d_in, const int* in_sizes, int n_in,
                              void* d_out, int out_size) {
    const float* m = (const float*)d_in[0];
    const float* v = (const float*)d_in[1];
    const float* W = (const float*)d_in[2];
    const float* b = (const float*)d_in[3];
    float* out = (float*)d_out;

    vt_prep<<<1024, 128>>>(v);
    cudaFuncSetAttribute(attn_mma, cudaFuncAttributeMaxDynamicSharedMemorySize,
                         (int)SMEM_BYTES);
    attn_mma<<<1024, NT, SMEM_BYTES>>>(m, W, b, out);
}

// round 7
// speedup vs baseline: 2.3782x; 1.0301x over previous
#include <cuda_runtime.h>
#include <cuda_bf16.h>
#include <cstdint>

typedef unsigned int u32; typedef unsigned short u16;

// AttentionMV B=T=1024, E=128, via mma.sync bf16 (3-pass split) fallback HMMA.
//  GEMM1 (per 64-t tile): D1[f][t] = sum_e WT[f][e]*m[t][e]
//  u = tanh(D1 + b[t][f]) -> bf16 hi/lo in REGISTERS (fragment-layout match)
//  GEMM2: pre[e][f] += sum_t vT[e][t]*u[t][f]   (reg accum, all tiles)
//  softmax over f per e-row; out[f] = sum_e (colsum_e/sumexp_e)*exp(pre[e][f]-mx_e)
// R7: MMA issue reordered pass-major so same-accumulator MMAs are >=8 apart.

constexpr int NT = 256;
constexpr u32 WTH=0, WTL=34816, MH=69632, ML=87040, VTH=104448, VTL=122880;
constexpr u32 SP_OFF=141312;
constexpr u32 CF_OFF=SP_OFF+4096;
constexpr u32 SMEM_BYTES=CF_OFF+512+64;
constexpr u32 P_OFF=0;
constexpr u32 EX_OFF=69632;

__device__ u16 g_vtH[128*1024];
__device__ u16 g_vtL[128*1024];

__device__ __forceinline__ float fast_tanh(float x){
    float e = __expf(2.0f*x);
    return 1.0f - __fdividef(2.0f, e+1.0f);
}
__device__ __forceinline__ void bsplit(float x, u16& h, u16& l){
    __nv_bfloat16 hb = __float2bfloat16(x);
    h = __bfloat16_as_ushort(hb);
    l = __bfloat16_as_ushort(__float2bfloat16(x - __bfloat162float(hb)));
}
__device__ __forceinline__ void mma16816(float* d, u32 a0,u32 a1,u32 a2,u32 a3,
                                         u32 b0,u32 b1){
    asm volatile("mma.sync.aligned.m16n8k16.row.col.f32.bf16.bf16.f32 "
        "{%0,%1,%2,%3}, {%4,%5,%6,%7}, {%8,%9}, {%0,%1,%2,%3};"
        : "+f"(d[0]),"+f"(d[1]),"+f"(d[2]),"+f"(d[3])
        : "r"(a0),"r"(a1),"r"(a2),"r"(a3),"r"(b0),"r"(b1));
}

__global__ void vt_prep(const float* __restrict__ gv){
    int t = blockIdx.x, e = threadIdx.x;
    u16 h,l; bsplit(gv[t*128+e], h, l);
    g_vtH[e*1024+t]=h; g_vtL[e*1024+t]=l;
}

__global__ __launch_bounds__(NT,1)
void attn_mma(const float* __restrict__ gm, const float* __restrict__ gW,
              const float* __restrict__ gb, float* __restrict__ gout)
{
    extern __shared__ char sm[];
    const int tid=threadIdx.x, lane=tid&31, w=tid>>5, bb=blockIdx.x;
    const int q=lane>>2, r2=(lane&3)*2;
    const float* Wb = gW + (size_t)bb*16384;
    const float4* mb4 = (const float4*)(gm + (size_t)bb*131072);

    // W -> WT[f][e] hi/lo bf16 (transposed, stride 136)
    for (int idx=tid; idx<16384; idx+=NT){
        int e=idx>>7, f=idx&127;
        u16 h,l; bsplit(__ldg(Wb+idx), h, l);
        *(u16*)(sm + WTH + (u32)(f*136+e)*2) = h;
        *(u16*)(sm + WTL + (u32)(f*136+e)*2) = l;
    }

    float4 mreg[8];
    #pragma unroll
    for (int i=0;i<8;i++) mreg[i] = __ldg(mb4 + i*NT + tid);

    float pre[8][2][4];
    #pragma unroll
    for (int i=0;i<8;i++)
        #pragma unroll
        for (int fb=0;fb<2;fb++)
            #pragma unroll
            for (int j=0;j<4;j++) pre[i][fb][j]=0.f;
    float s4[4]={0,0,0,0};

    for (int tile=0; tile<16; tile++){
        // m regs -> smem hi/lo + colsum
        #pragma unroll
        for (int i=0;i<8;i++){
            float4 x = mreg[i];
            s4[0]+=x.x; s4[1]+=x.y; s4[2]+=x.z; s4[3]+=x.w;
            u16 h0,l0,h1,l1,h2,l2,h3,l3;
            bsplit(x.x,h0,l0); bsplit(x.y,h1,l1);
            bsplit(x.z,h2,l2); bsplit(x.w,h3,l3);
            u32 off = (u32)((i*8+w)*136 + lane*4)*2;
            *(uint2*)(sm + MH + off) = make_uint2((u32)h0|((u32)h1<<16), (u32)h2|((u32)h3<<16));
            *(uint2*)(sm + ML + off) = make_uint2((u32)l0|((u32)l1<<16), (u32)l2|((u32)l3<<16));
        }
        // vT tile copy (pre-split gmem images)
        {
            const u16* srcH = g_vtH + tile*64;
            const u16* srcL = g_vtL + tile*64;
            #pragma unroll
            for (int i=0;i<8;i++){
                int j = i*NT + tid;
                int e = j>>4, tq = (j&15)*4;
                *(uint2*)(sm + VTH + (u32)(e*72+tq)*2) = *(const uint2*)(srcH + e*1024 + tq);
                *(uint2*)(sm + VTL + (u32)(e*72+tq)*2) = *(const uint2*)(srcL + e*1024 + tq);
            }
        }
        __syncthreads();
        if (tile<15){
            #pragma unroll
            for (int i=0;i<8;i++) mreg[i] = __ldg(mb4 + (tile+1)*2048 + i*NT + tid);
        }

        // ---- GEMM1: warp w -> f rows w*16..+15, t cols 0..63
        // Pass-major issue: same d1[nb] re-used only every 8 MMAs.
        float d1[8][4];
        #pragma unroll
        for (int nb=0;nb<8;nb++){ d1[nb][0]=0;d1[nb][1]=0;d1[nb][2]=0;d1[nb][3]=0; }
        #pragma unroll
        for (int ks=0;ks<8;ks++){
            u32 ar = (u32)((w*16+q)*136 + ks*16 + r2);
            u32 ah0=*(u32*)(sm+WTH+ar*2),        ah1=*(u32*)(sm+WTH+(ar+8*136)*2);
            u32 ah2=*(u32*)(sm+WTH+(ar+8)*2),    ah3=*(u32*)(sm+WTH+(ar+8*136+8)*2);
            u32 al0=*(u32*)(sm+WTL+ar*2),        al1=*(u32*)(sm+WTL+(ar+8*136)*2);
            u32 al2=*(u32*)(sm+WTL+(ar+8)*2),    al3=*(u32*)(sm+WTL+(ar+8*136+8)*2);
            u32 bh[8][2], bl[8][2];
            #pragma unroll
            for (int nb=0;nb<8;nb++){
                u32 boff = (u32)((nb*8+q)*136 + ks*16 + r2)*2;
                bh[nb][0]=*(u32*)(sm+MH+boff); bh[nb][1]=*(u32*)(sm+MH+boff+16);
                bl[nb][0]=*(u32*)(sm+ML+boff); bl[nb][1]=*(u32*)(sm+ML+boff+16);
            }
            #pragma unroll
            for (int nb=0;nb<8;nb++)
                mma16816(d1[nb], ah0,ah1,ah2,ah3, bh[nb][0],bh[nb][1]);
            #pragma unroll
            for (int nb=0;nb<8;nb++)
                mma16816(d1[nb], ah0,ah1,ah2,ah3, bl[nb][0],bl[nb][1]);
            #pragma unroll
            for (int nb=0;nb<8;nb++)
                mma16816(d1[nb], al0,al1,al2,al3, bh[nb][0],bh[nb][1]);
        }

        // ---- bias + tanh + bf16 split (registers only)
        u32 uh[8][2], ul[8][2];
        #pragma unroll
        for (int nb=0;nb<8;nb++){
            int t0 = tile*64 + nb*8 + r2;
            int f0 = w*16 + q;
            const float* bp = gb + (size_t)t0*128;
            float u0=fast_tanh(d1[nb][0]+__ldg(bp+f0));
            float u1=fast_tanh(d1[nb][1]+__ldg(bp+128+f0));
            float u2=fast_tanh(d1[nb][2]+__ldg(bp+f0+8));
            float u3=fast_tanh(d1[nb][3]+__ldg(bp+128+f0+8));
            u16 h0,l0,h1,l1,h2,l2,h3,l3;
            bsplit(u0,h0,l0); bsplit(u1,h1,l1); bsplit(u2,h2,l2); bsplit(u3,h3,l3);
            uh[nb][0]=(u32)h0|((u32)h1<<16); ul[nb][0]=(u32)l0|((u32)l1<<16);
            uh[nb][1]=(u32)h2|((u32)h3<<16); ul[nb][1]=(u32)l2|((u32)l3<<16);
        }

        // ---- GEMM2: pass-major over i-quads: same pre[i][fb] every 8 MMAs.
        #pragma unroll
        for (int s=0;s<4;s++){
            #pragma unroll
            for (int iq=0;iq<2;iq++){
                u32 ah[4][4], al[4][4];
                #pragma unroll
                for (int ii=0;ii<4;ii++){
                    int i = iq*4+ii;
                    u32 ar = (u32)((i*16+q)*72 + s*16 + r2);
                    ah[ii][0]=*(u32*)(sm+VTH+ar*2);
                    ah[ii][1]=*(u32*)(sm+VTH+(ar+8*72)*2);
                    ah[ii][2]=*(u32*)(sm+VTH+(ar+8)*2);
                    ah[ii][3]=*(u32*)(sm+VTH+(ar+8*72+8)*2);
                    al[ii][0]=*(u32*)(sm+VTL+ar*2);
                    al[ii][1]=*(u32*)(sm+VTL+(ar+8*72)*2);
                    al[ii][2]=*(u32*)(sm+VTL+(ar+8)*2);
                    al[ii][3]=*(u32*)(sm+VTL+(ar+8*72+8)*2);
                }
                #pragma unroll
                for (int ii=0;ii<4;ii++)
                    #pragma unroll
                    for (int fb=0;fb<2;fb++)
                        mma16816(pre[iq*4+ii][fb], ah[ii][0],ah[ii][1],ah[ii][2],ah[ii][3],
                                 uh[2*s][fb], uh[2*s+1][fb]);
                #pragma unroll
                for (int ii=0;ii<4;ii++)
                    #pragma unroll
                    for (int fb=0;fb<2;fb++)
                        mma16816(pre[iq*4+ii][fb], ah[ii][0],ah[ii][1],ah[ii][2],ah[ii][3],
                                 ul[2*s][fb], ul[2*s+1][fb]);
                #pragma unroll
                for (int ii=0;ii<4;ii++)
                    #pragma unroll
                    for (int fb=0;fb<2;fb++)
                        mma16816(pre[iq*4+ii][fb], al[ii][0],al[ii][1],al[ii][2],al[ii][3],
                                 uh[2*s][fb], uh[2*s+1][fb]);
            }
        }
        __syncthreads();
    }

    // ---- epilogue
    float* P = (float*)(sm + P_OFF);
    #pragma unroll
    for (int i=0;i<8;i++)
        #pragma unroll
        for (int fb=0;fb<2;fb++){
            int e0 = i*16+q, f0 = w*16+fb*8+r2;
            P[e0*132+f0]     = pre[i][fb][0];
            P[e0*132+f0+1]   = pre[i][fb][1];
            P[(e0+8)*132+f0]   = pre[i][fb][2];
            P[(e0+8)*132+f0+1] = pre[i][fb][3];
        }
    float* SP=(float*)(sm+SP_OFF);
    *(float4*)(SP + w*128 + lane*4) = make_float4(s4[0],s4[1],s4[2],s4[3]);
    __syncthreads();

    float* EX=(float*)(sm+EX_OFF);
    float* CF=(float*)(sm+CF_OFF);
    if (tid<128){
        int e=tid;
        float ss=0;
        #pragma unroll
        for (int ww=0;ww<8;ww++) ss+=SP[ww*128+e];
        float mx=-1e30f;
        #pragma unroll 8
        for (int f=0;f<128;f++) mx=fmaxf(mx,P[e*132+f]);
        float sum=0;
        #pragma unroll 4
        for (int f=0;f<128;f++){
            float ex=__expf(P[e*132+f]-mx);
            sum+=ex; EX[f*132+e]=ex;
        }
        CF[e]=ss*__fdividef(1.f,sum);
    }
    __syncthreads();
    if (tid<128){
        int f=tid; float acc=0;
        #pragma unroll 8
        for (int e=0;e<128;e++) acc=fmaf(CF[e],EX[f*132+e],acc);
        gout[(size_t)bb*128+f]=acc;
    }
}

extern "C" void kernel_launch(void* const* d_in, const int* in_sizes, int n_in,
                              void* d_out, int out_size) {
    const float* m = (const float*)d_in[0];
    const float* v = (const float*)d_in[1];
    const float* W = (const float*)d_in[2];
    const float* b = (const float*)d_in[3];
    float* out = (float*)d_out;

    vt_prep<<<1024, 128>>>(v);
    cudaFuncSetAttribute(attn_mma, cudaFuncAttributeMaxDynamicSharedMemorySize,
                         (int)SMEM_BYTES);
    attn_mma<<<1024, NT, SMEM_BYTES>>>(m, W, b, out);
}

// round 9
// speedup vs baseline: 2.5428x; 1.0692x over previous
#include <cuda_runtime.h>
#include <cuda_bf16.h>
#include <cstdint>

typedef unsigned int u32; typedef unsigned short u16;

// AttentionMV B=T=1024, E=128. mma.sync bf16 3-pass split.
// R8/R9: fragment-native smem layouts (LDS.128/LDS.64 operand fetch),
//     truncation-based hi/lo splits (prmt + bf16x2 cvt), cp.async vT prefetch.
//  GEMM1 (per 64-t tile): D1[f][t] = sum_e WT[f][e]*m[t][e]
//  u = tanh(D1+b) -> bf16 hi/lo in registers (accum layout == B-frag layout)
//  GEMM2: pre[e][f] += sum_t vT[e][t]*u[t][f]  (reg accum over all tiles)

constexpr int NT = 256;
// smem byte offsets
constexpr u32 WFH = 0;          // W frag hi: 64 blk * 512B = 32KB
constexpr u32 WFL = 32768;
constexpr u32 MFH = 65536;      // m frag hi: 64 blk * 256B = 16KB
constexpr u32 MFL = 81920;
constexpr u32 VT0 = 98304;      // vT frag buf0: hi 16KB + lo 16KB
constexpr u32 VT1 = 131072;
// epilogue aliases (post-loop): P@0 (128*132*4), EX@98304 (128*132*4)
constexpr u32 P_OFF  = 0;
constexpr u32 EX_OFF = 98304;
constexpr u32 SP_OFF = 165888;  // 8*128 f32
constexpr u32 CF_OFF = 169984;  // 128 f32
constexpr u32 SMEM_BYTES = 170496;

__device__ u16 g_vtFH[131072];   // vT A-frag images, per tile 16KB
__device__ u16 g_vtFL[131072];

__device__ __forceinline__ float fast_tanh(float x){
    float e = __expf(2.0f*x);
    return 1.0f - __fdividef(2.0f, e+1.0f);
}
__device__ __forceinline__ float trunc_hi(float x){
    return __uint_as_float(__float_as_uint(x) & 0xffff0000u);
}
__device__ __forceinline__ u32 cvt_bf16x2(float hiArg, float loArg){
    u32 d; asm("cvt.rn.bf16x2.f32 %0, %1, %2;" : "=r"(d) : "f"(hiArg), "f"(loArg));
    return d;
}
__device__ __forceinline__ void mma16816(float* d, u32 a0,u32 a1,u32 a2,u32 a3,
                                         u32 b0,u32 b1){
    asm volatile("mma.sync.aligned.m16n8k16.row.col.f32.bf16.bf16.f32 "
        "{%0,%1,%2,%3}, {%4,%5,%6,%7}, {%8,%9}, {%0,%1,%2,%3};"
        : "+f"(d[0]),"+f"(d[1]),"+f"(d[2]),"+f"(d[3])
        : "r"(a0),"r"(a1),"r"(a2),"r"(a3),"r"(b0),"r"(b1));
}
__device__ __forceinline__ u32 smem_u32(const void* p){
    u32 a; asm("{ .reg .u64 t; cvta.to.shared.u64 t, %1; cvt.u32.u64 %0, t; }"
               : "=r"(a) : "l"(p));
    return a;
}
__device__ __forceinline__ void cp16(u32 dst, const void* src){
    asm volatile("cp.async.ca.shared.global [%0], [%1], 16;" :: "r"(dst), "l"(src));
}

// vT A-frag prep: a-frag for A[m=e][k=t], m16k16 blocks (i = e/16, s = (t%64)/16)
__global__ void vt_prep(const float* __restrict__ gv){
    int t = blockIdx.x, e = threadIdx.x;
    float x = gv[t*128 + e];
    u16 hi = (u16)(__float_as_uint(x) >> 16);
    u16 lo = __bfloat16_as_ushort(__float2bfloat16(x - trunc_hi(x)));
    int tile = t>>6, s = (t>>4)&3, tr = t&15;
    int kh = tr>>3, rs = (tr&7)>>1, byt = tr&1;
    int i = e>>4, eq = e&15, rh = eq>>3, q = eq&7;
    int reg = rh + 2*kh, lane = q*4 + rs;
    int idx = ((tile*32 + i*4 + s)*32 + lane)*8 + reg*2 + byt;
    g_vtFH[idx] = hi; g_vtFL[idx] = lo;
}

__global__ __launch_bounds__(NT,1)
void attn_mma(const float* __restrict__ gm, const float* __restrict__ gW,
              const float* __restrict__ gb, float* __restrict__ gout)
{
    extern __shared__ char sm[];
    const u32 sbase = smem_u32(sm);
    const int tid=threadIdx.x, lane=tid&31, w=tid>>5, bb=blockIdx.x;
    const int q=lane>>2, r2=(lane&3)*2;
    const float* Wb = gW + (size_t)bb*16384;
    const float4* mb4 = (const float4*)(gm + (size_t)bb*131072);

    // ---- W -> A-frag layout (WT[f][e], m16k16 blocks (w2 = f/16, ks = e/16))
    for (int it=0; it<64; it++){
        int idx = it*NT + tid;
        int e = idx>>7, f = idx&127;
        float x = __ldg(Wb + idx);
        u16 hi = (u16)(__float_as_uint(x) >> 16);
        u16 lo = __bfloat16_as_ushort(__float2bfloat16(x - trunc_hi(x)));
        int w2=f>>4, fr=f&15, rh=fr>>3, qq=fr&7;
        int ks=e>>4, er=e&15, kh=er>>3, rs=(er&7)>>1, byt=er&1;
        u32 off = (u32)(((w2*8+ks)*32 + qq*4 + rs)*16 + (rh + 2*kh)*4 + byt*2);
        *(u16*)(sm + WFH + off) = hi;
        *(u16*)(sm + WFL + off) = lo;
    }

    // prologue: cp vT(0), load m tile0
    {
        const char* srcH = (const char*)g_vtFH;
        const char* srcL = (const char*)g_vtFL;
        #pragma unroll
        for (int k2=0;k2<4;k2++){
            cp16(sbase + VT0 + tid*64 + k2*16,         srcH + tid*64 + k2*16);
            cp16(sbase + VT0 + 16384 + tid*64 + k2*16, srcL + tid*64 + k2*16);
        }
        asm volatile("cp.async.commit_group;");
    }
    float4 mreg[8];
    #pragma unroll
    for (int j=0;j<8;j++) mreg[j] = __ldg(mb4 + j*NT + tid);

    float pre[8][2][4];
    #pragma unroll
    for (int i=0;i<8;i++)
        #pragma unroll
        for (int fb=0;fb<2;fb++)
            #pragma unroll
            for (int j2=0;j2<4;j2++) pre[i][fb][j2]=0.f;
    float s4[4]={0,0,0,0};

    const int m_ks = lane>>2, m_r = (lane>>1)&1, m_lsub = (lane&1)*2;

    for (int tile=0; tile<16; tile++){
        const u32 VTp = (tile&1) ? VT1 : VT0;

        // ---- m split -> B-frag layout (uses mreg = tile's data) + colsum
        #pragma unroll
        for (int j=0;j<8;j++){
            float4 x = mreg[j];
            s4[0]+=x.x; s4[1]+=x.y; s4[2]+=x.z; s4[3]+=x.w;
            u32 hA = __byte_perm(__float_as_uint(x.x), __float_as_uint(x.y), 0x7632);
            u32 hB = __byte_perm(__float_as_uint(x.z), __float_as_uint(x.w), 0x7632);
            float l0 = x.x - trunc_hi(x.x), l1 = x.y - trunc_hi(x.y);
            float l2 = x.z - trunc_hi(x.z), l3 = x.w - trunc_hi(x.w);
            u32 lA = cvt_bf16x2(l1, l0), lB = cvt_bf16x2(l3, l2);
            int l  = w*4 + m_lsub;                    // frag-lane (q = t&7 = w)
            u32 base = (u32)((j*8 + m_ks) << 8);
            u32 pA = (u32)((l*2     + m_r + m_ks*8) & 63)*4;
            u32 pB = (u32)(((l+1)*2 + m_r + m_ks*8) & 63)*4;
            *(u32*)(sm + MFH + base + pA) = hA;
            *(u32*)(sm + MFH + base + pB) = hB;
            *(u32*)(sm + MFL + base + pA) = lA;
            *(u32*)(sm + MFL + base + pB) = lB;
        }
        if (tile<15){
            #pragma unroll
            for (int j=0;j<8;j++) mreg[j] = __ldg(mb4 + (tile+1)*2048 + j*NT + tid);
        }
        __syncthreads();                 // A: m frags ready; prev GEMM2 done

        // cp vT(tile+1)
        if (tile<15){
            const u32 VTn = (tile&1) ? VT0 : VT1;
            const char* srcH = (const char*)g_vtFH + (tile+1)*16384;
            const char* srcL = (const char*)g_vtFL + (tile+1)*16384;
            #pragma unroll
            for (int k2=0;k2<4;k2++){
                cp16(sbase + VTn + tid*64 + k2*16,         srcH + tid*64 + k2*16);
                cp16(sbase + VTn + 16384 + tid*64 + k2*16, srcL + tid*64 + k2*16);
            }
        }
        asm volatile("cp.async.commit_group;");

        // ---- GEMM1: warp w -> f rows w*16..+15, t cols 0..63
        float d1[8][4];
        #pragma unroll
        for (int nb=0;nb<8;nb++){ d1[nb][0]=0;d1[nb][1]=0;d1[nb][2]=0;d1[nb][3]=0; }
        #pragma unroll
        for (int ks=0;ks<8;ks++){
            uint4 ahv = *(const uint4*)(sm + WFH + (u32)(((w*8+ks)*32+lane)*16));
            uint4 alv = *(const uint4*)(sm + WFL + (u32)(((w*8+ks)*32+lane)*16));
            u32 bh[8][2], bl[8][2];
            u32 bpos = (u32)(((lane*2) + ks*8) & 63)*4;
            #pragma unroll
            for (int nb=0;nb<8;nb++){
                uint2 t2 = *(const uint2*)(sm + MFH + (u32)((nb*8+ks)<<8) + bpos);
                bh[nb][0]=t2.x; bh[nb][1]=t2.y;
                uint2 t3 = *(const uint2*)(sm + MFL + (u32)((nb*8+ks)<<8) + bpos);
                bl[nb][0]=t3.x; bl[nb][1]=t3.y;
            }
            #pragma unroll
            for (int nb=0;nb<8;nb++)
                mma16816(d1[nb], ahv.x,ahv.y,ahv.z,ahv.w, bh[nb][0],bh[nb][1]);
            #pragma unroll
            for (int nb=0;nb<8;nb++)
                mma16816(d1[nb], ahv.x,ahv.y,ahv.z,ahv.w, bl[nb][0],bl[nb][1]);
            #pragma unroll
            for (int nb=0;nb<8;nb++)
                mma16816(d1[nb], alv.x,alv.y,alv.z,alv.w, bh[nb][0],bh[nb][1]);
        }

        // ---- bias + tanh + split (registers only)
        u32 uh[8][2], ul[8][2];
        #pragma unroll
        for (int nb=0;nb<8;nb++){
            int t0 = tile*64 + nb*8 + r2;
            int f0 = w*16 + q;
            const float* bp = gb + (size_t)t0*128;
            float u0=fast_tanh(d1[nb][0]+__ldg(bp+f0));
            float u1=fast_tanh(d1[nb][1]+__ldg(bp+128+f0));
            float u2=fast_tanh(d1[nb][2]+__ldg(bp+f0+8));
            float u3=fast_tanh(d1[nb][3]+__ldg(bp+128+f0+8));
            uh[nb][0] = __byte_perm(__float_as_uint(u0), __float_as_uint(u1), 0x7632);
            uh[nb][1] = __byte_perm(__float_as_uint(u2), __float_as_uint(u3), 0x7632);
            ul[nb][0] = cvt_bf16x2(u1 - trunc_hi(u1), u0 - trunc_hi(u0));
            ul[nb][1] = cvt_bf16x2(u3 - trunc_hi(u3), u2 - trunc_hi(u2));
        }

        asm volatile("cp.async.wait_group 1;");
        __syncthreads();                 // B: vT(tile) visible; GEMM1 reads done

        // ---- GEMM2: pass-major, i-quads
        #pragma unroll
        for (int s=0;s<4;s++){
            #pragma unroll
            for (int iq=0;iq<2;iq++){
                u32 ah[4][4], al[4][4];
                #pragma unroll
                for (int ii=0;ii<4;ii++){
                    int i = iq*4+ii;
                    uint4 a4 = *(const uint4*)(sm + VTp + (u32)(((i*4+s)*32+lane)*16));
                    ah[ii][0]=a4.x; ah[ii][1]=a4.y; ah[ii][2]=a4.z; ah[ii][3]=a4.w;
                    uint4 a5 = *(const uint4*)(sm + VTp + 16384 + (u32)(((i*4+s)*32+lane)*16));
                    al[ii][0]=a5.x; al[ii][1]=a5.y; al[ii][2]=a5.z; al[ii][3]=a5.w;
                }
                #pragma unroll
                for (int ii=0;ii<4;ii++)
                    #pragma unroll
                    for (int fb=0;fb<2;fb++)
                        mma16816(pre[iq*4+ii][fb], ah[ii][0],ah[ii][1],ah[ii][2],ah[ii][3],
                                 uh[2*s][fb], uh[2*s+1][fb]);
                #pragma unroll
                for (int ii=0;ii<4;ii++)
                    #pragma unroll
                    for (int fb=0;fb<2;fb++)
                        mma16816(pre[iq*4+ii][fb], ah[ii][0],ah[ii][1],ah[ii][2],ah[ii][3],
                                 ul[2*s][fb], ul[2*s+1][fb]);
                #pragma unroll
                for (int ii=0;ii<4;ii++)
                    #pragma unroll
                    for (int fb=0;fb<2;fb++)
                        mma16816(pre[iq*4+ii][fb], al[ii][0],al[ii][1],al[ii][2],al[ii][3],
                                 uh[2*s][fb], uh[2*s+1][fb]);
            }
        }
    }
    __syncthreads();

    // ---- epilogue
    float* P = (float*)(sm + P_OFF);
    #pragma unroll
    for (int i=0;i<8;i++)
        #pragma unroll
        for (int fb=0;fb<2;fb++){
            int e0 = i*16+q, f0 = w*16+fb*8+r2;
            P[e0*132+f0]       = pre[i][fb][0];
            P[e0*132+f0+1]     = pre[i][fb][1];
            P[(e0+8)*132+f0]   = pre[i][fb][2];
            P[(e0+8)*132+f0+1] = pre[i][fb][3];
        }
    float* SP=(float*)(sm+SP_OFF);
    *(float4*)(SP + w*128 + lane*4) = make_float4(s4[0],s4[1],s4[2],s4[3]);
    __syncthreads();

    float* EX=(float*)(sm+EX_OFF);
    float* CF=(float*)(sm+CF_OFF);
    if (tid<128){
        int e=tid;
        float ss=0;
        #pragma unroll
        for (int ww=0;ww<8;ww++) ss+=SP[ww*128+e];
        float mx=-1e30f;
        #pragma unroll 8
        for (int f=0;f<128;f++) mx=fmaxf(mx,P[e*132+f]);
        float sum=0;
        #pragma unroll 4
        for (int f=0;f<128;f++){
            float ex=__expf(P[e*132+f]-mx);
            sum+=ex; EX[f*132+e]=ex;
        }
        CF[e]=ss*__fdividef(1.f,sum);
    }
    __syncthreads();
    if (tid<128){
        int f=tid; float acc=0;
        #pragma unroll 8
        for (int e=0;e<128;e++) acc=fmaf(CF[e],EX[f*132+e],acc);
        gout[(size_t)bb*128+f]=acc;
    }
}

extern "C" void kernel_launch(void* const* d_in, const int* in_sizes, int n_in,
                              void* d_out, int out_size) {
    const float* m = (const float*)d_in[0];
    const float* v = (const float*)d_in[1];
    const float* W = (const float*)d_in[2];
    const float* b = (const float*)d_in[3];
    float* out = (float*)d_out;

    vt_prep<<<1024, 128>>>(v);
    cudaFuncSetAttribute(attn_mma, cudaFuncAttributeMaxDynamicSharedMemorySize,
                         (int)SMEM_BYTES);
    attn_mma<<<1024, NT, SMEM_BYTES>>>(m, W, b, out);
}